// round 15
// baseline (speedup 1.0000x reference)
#include <cuda_runtime.h>
#include <math.h>

#define B_  4
#define S_  2048
#define D_  1280
#define H_  16
#define HD_ 80
#define NQKV (3 * H_ * HD_)   // 3840

// Scratch (allocation-free rule: __device__ globals)
__device__ float g_qkv[(size_t)B_ * S_ * NQKV];        // 126 MB (tf32-rounded)
__device__ float g_attn[(size_t)B_ * S_ * H_ * HD_];   // 42 MB (tf32-rounded)
__device__ float g_hid[(size_t)B_ * S_ * D_];          // 42 MB (tf32-rounded)
__device__ float g_qkvw[(size_t)NQKV * D_];            // 19.7 MB (tf32-rounded)
__device__ float g_ow[(size_t)D_ * (H_ * HD_)];        // 6.6 MB (tf32-rounded)
__device__ float g_qscale[HD_];

// ---------------------------------------------------------------------------
// Helpers
// ---------------------------------------------------------------------------
__device__ __forceinline__ unsigned f2tf(float x) {
    unsigned r;
    asm("cvt.rna.tf32.f32 %0, %1;" : "=r"(r) : "f"(x));
    return r;
}
__device__ __forceinline__ float f2tff(float x) {
    return __uint_as_float(f2tf(x));
}
__device__ __forceinline__ void mma_tf32(float* d, const unsigned* a,
                                         unsigned b0, unsigned b1) {
    asm volatile(
        "mma.sync.aligned.m16n8k8.row.col.f32.tf32.tf32.f32 "
        "{%0,%1,%2,%3}, {%4,%5,%6,%7}, {%8,%9}, {%0,%1,%2,%3};"
        : "+f"(d[0]), "+f"(d[1]), "+f"(d[2]), "+f"(d[3])
        : "r"(a[0]), "r"(a[1]), "r"(a[2]), "r"(a[3]), "r"(b0), "r"(b1));
}
__device__ __forceinline__ void cp_async16(unsigned dst, const float* src) {
    asm volatile("cp.async.cg.shared.global [%0], [%1], 16;"
                 :: "r"(dst), "l"(src));
}
__device__ __forceinline__ void cp_commit() {
    asm volatile("cp.async.commit_group;");
}
template <int N>
__device__ __forceinline__ void cp_wait() {
    asm volatile("cp.async.wait_group %0;" :: "n"(N));
}

// ---------------------------------------------------------------------------
// Pre-pass: tf32-round an fp32 array (element count divisible by 4)
// ---------------------------------------------------------------------------
__global__ void cvt_tf32_kernel(const float* __restrict__ src,
                                float* __restrict__ dst, int n4) {
    int i = blockIdx.x * blockDim.x + threadIdx.x;
    if (i < n4) {
        float4 v = ((const float4*)src)[i];
        ((float4*)dst)[i] = make_float4(f2tff(v.x), f2tff(v.y),
                                        f2tff(v.z), f2tff(v.w));
    }
}

// ---------------------------------------------------------------------------
// Per-dim query scale: softplus(scaling) * log2(e) / sqrt(HD)
// ---------------------------------------------------------------------------
__global__ void qscale_kernel(const float* __restrict__ scaling) {
    int i = threadIdx.x;
    if (i < HD_) {
        float x = scaling[i];
        float sp = (x > 20.f) ? x : log1pf(expf(x));
        g_qscale[i] = sp * 1.4426950408889634f * rsqrtf((float)HD_);
    }
}

// ---------------------------------------------------------------------------
// TF32 tensor-core GEMM: cp.async pipeline with PAIR-granularity barriers.
// 4 stage-buffers = 2 pair-buffers (32-k each). Per iteration: one wait +
// one __syncthreads + one commit, then 2 stages (64 HMMA/warp) of compute.
// Halves sync cadence vs R10/R13 at identical smem (2-CTA residency kept).
// C = A·B^T + bias; A,B K-major, pre-rounded to tf32. 128x128 tile,
// 256 threads, warp tile 32x64, m16n8k8. smem [row][k] stride 20;
// fragment LDS banks (20g+c) all-distinct. Requires K % 32 == 0.
// ROUND_OUT: tf32-round epilogue output (QKV -> flash consumption).
// ---------------------------------------------------------------------------
#define GST  20
#define GSTG (128 * GST)            // 2560 floats per operand-stage
#define NSTG 4
#define GEMM_SMEM (2 * NSTG * GSTG * 4)   // 81920 B

template <int APPLY_QSCALE, int ROUND_OUT>
__global__ __launch_bounds__(256, 2)
void gemm_tf32(const float* __restrict__ A, const float* __restrict__ Bm,
               const float* __restrict__ bias, float* __restrict__ C,
               int M, int N, int K) {
    extern __shared__ float gsm[];
    float* smA = gsm;                    // [NSTG][128][GST]
    float* smB = gsm + NSTG * GSTG;

    const int tid  = threadIdx.x;
    const int lane = tid & 31;
    const int wid  = tid >> 5;
    const int wm   = wid & 3;
    const int wn   = wid >> 2;
    const int g    = lane >> 2;
    const int c    = lane & 3;

    const int m0 = blockIdx.y * 128;
    const int n0 = blockIdx.x * 128;

    const int lrow = tid >> 1;       // 0..127
    const int lc   = (tid & 1) * 8;  // 0 or 8

    const float* Ap = A  + (size_t)(m0 + lrow) * K + lc;
    const float* Bp = Bm + (size_t)(n0 + lrow) * K + lc;

    const unsigned sA = (unsigned)__cvta_generic_to_shared(smA)
                        + (lrow * GST + lc) * 4;
    const unsigned sB = (unsigned)__cvta_generic_to_shared(smB)
                        + (lrow * GST + lc) * 4;

    float acc[2][8][4];
#pragma unroll
    for (int i = 0; i < 2; ++i)
#pragma unroll
        for (int j = 0; j < 8; ++j)
#pragma unroll
            for (int q = 0; q < 4; ++q) acc[i][j][q] = 0.f;

    const int pairs = K >> 5;   // 32-k pairs (K=1280 -> 40)

    // prologue: pair 0 (stages 0,1) as ONE commit group
#pragma unroll
    for (int s = 0; s < 2; ++s) {
        const int k0 = s * 16;
        cp_async16(sA + s * GSTG * 4,      Ap + k0);
        cp_async16(sA + s * GSTG * 4 + 16, Ap + k0 + 4);
        cp_async16(sB + s * GSTG * 4,      Bp + k0);
        cp_async16(sB + s * GSTG * 4 + 16, Bp + k0 + 4);
    }
    cp_commit();

    for (int p = 0; p < pairs; ++p) {
        // exactly one group (pair p) outstanding here
        cp_wait<0>();
        __syncthreads();

        // prefetch pair p+1 into the other pair-buffer (held pair p-1;
        // all warps finished it at the barrier above)
        if (p + 1 < pairs) {
            const int base = ((p + 1) & 1) * 2;
            const int k0 = (p + 1) * 32;
#pragma unroll
            for (int s = 0; s < 2; ++s) {
                cp_async16(sA + (base + s) * GSTG * 4,      Ap + k0 + s * 16);
                cp_async16(sA + (base + s) * GSTG * 4 + 16, Ap + k0 + s * 16 + 4);
                cp_async16(sB + (base + s) * GSTG * 4,      Bp + k0 + s * 16);
                cp_async16(sB + (base + s) * GSTG * 4 + 16, Bp + k0 + s * 16 + 4);
            }
        }
        cp_commit();

        // compute pair p: stages at buffers (p&1)*2 and (p&1)*2+1
#pragma unroll
        for (int half = 0; half < 2; ++half) {
            const int st = (p & 1) * 2 + half;
            const float* Asp = &smA[st * GSTG];
            const float* Bsp = &smB[st * GSTG];
#pragma unroll
            for (int ks = 0; ks < 2; ++ks) {
                const int kk = ks * 8;
                unsigned af[2][4];
#pragma unroll
                for (int ii = 0; ii < 2; ++ii) {
                    const float* ab = &Asp[(wm * 32 + ii * 16 + g) * GST + kk + c];
                    af[ii][0] = __float_as_uint(ab[0]);
                    af[ii][1] = __float_as_uint(ab[8 * GST]);
                    af[ii][2] = __float_as_uint(ab[4]);
                    af[ii][3] = __float_as_uint(ab[8 * GST + 4]);
                }
#pragma unroll
                for (int j = 0; j < 8; ++j) {
                    const float* bb = &Bsp[(wn * 64 + j * 8 + g) * GST + kk + c];
                    unsigned b0 = __float_as_uint(bb[0]);
                    unsigned b1 = __float_as_uint(bb[4]);
                    mma_tf32(acc[0][j], af[0], b0, b1);
                    mma_tf32(acc[1][j], af[1], b0, b1);
                }
            }
        }
    }

    // Epilogue: + bias, optional Q scaling, optional tf32 rounding
#pragma unroll
    for (int j = 0; j < 8; ++j) {
        const int col = n0 + wn * 64 + j * 8 + c * 2;
        float b0 = bias[col], b1 = bias[col + 1];
        float q0 = 1.f, q1 = 1.f;
        if (APPLY_QSCALE && col < H_ * HD_) {
            q0 = g_qscale[col % HD_];
            q1 = g_qscale[(col + 1) % HD_];
        }
#pragma unroll
        for (int i = 0; i < 2; ++i) {
            const int r0 = m0 + wm * 32 + i * 16 + g;
            float2 o0, o1;
            o0.x = (acc[i][j][0] + b0) * q0;
            o0.y = (acc[i][j][1] + b1) * q1;
            o1.x = (acc[i][j][2] + b0) * q0;
            o1.y = (acc[i][j][3] + b1) * q1;
            if (ROUND_OUT) {
                o0.x = f2tff(o0.x); o0.y = f2tff(o0.y);
                o1.x = f2tff(o1.x); o1.y = f2tff(o1.y);
            }
            *(float2*)&C[(size_t)r0 * N + col]       = o0;
            *(float2*)&C[(size_t)(r0 + 8) * N + col] = o1;
        }
    }
}

// ---------------------------------------------------------------------------
// Tensor-core causal flash attention (R13 config — measured best).
// g_qkv is tf32-rounded; staging is raw cp.async (no CVT).
// BQ=64 (4 warps x 16 rows), BK=64. 1280 16B-chunks per tile.
// Q,K row-major stride 84 (fragment banks 20g+c: distinct).
// V row-major stride 88 (fragment banks 24c+g: distinct).
// grid = (S/64 [reversed], H, B), block = 128.
// ---------------------------------------------------------------------------
#define QS_ST 84
#define KR_ST 84
#define VS_ST 88
#define P_ST  68
#define QS_FLOATS (64 * QS_ST)          // 5376
#define KR_FLOATS (64 * KR_ST)          // 5376
#define VS_FLOATS (64 * VS_ST)          // 5632
#define FL_SMEM_FLOATS (QS_FLOATS + KR_FLOATS + VS_FLOATS)   // 16384

__global__ __launch_bounds__(128, 2)
void flash_tc() {
    extern __shared__ float sm[];
    float* Qs = sm;                     // [64][84]; reused as P after Q->regs
    float* Kr = sm + QS_FLOATS;         // [64][84]
    float* Vs = Kr + KR_FLOATS;         // [64][88]

    const int t    = threadIdx.x;
    const int lane = t & 31;
    const int wq   = t >> 5;
    const int g    = lane >> 2;
    const int c    = lane & 3;
    const int qt   = gridDim.x - 1 - blockIdx.x;   // heavy blocks first
    const int q0   = qt * 64;
    const int h    = blockIdx.y;
    const int b    = blockIdx.z;

    const unsigned sQ = (unsigned)__cvta_generic_to_shared(Qs);
    const unsigned sK = (unsigned)__cvta_generic_to_shared(Kr);
    const unsigned sV = (unsigned)__cvta_generic_to_shared(Vs);

    // Stage Q via cp.async: 64 rows x 20 16B-chunks = 1280 chunks
    {
        const float* qg = g_qkv + (size_t)(b * S_ + q0) * NQKV + h * HD_;
        for (int i = t; i < 1280; i += 128) {
            int r = i / 20, q4 = (i % 20) * 4;
            cp_async16(sQ + (r * QS_ST + q4) * 4, qg + (size_t)r * NQKV + q4);
        }
        cp_commit();
        cp_wait<0>();
        __syncthreads();
    }

    // Q fragments (A layout)
    unsigned qf[10][4];
#pragma unroll
    for (int kt = 0; kt < 10; ++kt) {
        const float* qp = &Qs[(wq * 16 + g) * QS_ST + kt * 8 + c];
        qf[kt][0] = __float_as_uint(qp[0]);
        qf[kt][1] = __float_as_uint(qp[8 * QS_ST]);
        qf[kt][2] = __float_as_uint(qp[4]);
        qf[kt][3] = __float_as_uint(qp[8 * QS_ST + 4]);
    }

    float m0 = -INFINITY, m1 = -INFINITY, l0 = 0.f, l1 = 0.f;
    float o[10][4];
#pragma unroll
    for (int j = 0; j < 10; ++j)
#pragma unroll
        for (int q = 0; q < 4; ++q) o[j][q] = 0.f;

    float* Pw = sm + wq * (16 * P_ST);   // warp-private, overlaps Qs (safe:
                                         // qf cached in regs before loop)

    const int ntiles = qt + 1;
    for (int kt0 = 0; kt0 < ntiles; ++kt0) {
        const int k0 = kt0 * 64;
        __syncthreads();   // previous tile fully consumed before overwrite
        // Stage K,V via cp.async: 1280 chunks each
        {
            const float* kg = g_qkv + (size_t)(b * S_ + k0) * NQKV
                              + H_ * HD_ + h * HD_;
            const float* vg = kg + H_ * HD_;
            for (int i = t; i < 1280; i += 128) {
                int r = i / 20, q4 = (i % 20) * 4;
                size_t off = (size_t)r * NQKV + q4;
                cp_async16(sK + (r * KR_ST + q4) * 4, kg + off);
                cp_async16(sV + (r * VS_ST + q4) * 4, vg + off);
            }
            cp_commit();
            cp_wait<0>();
            __syncthreads();
        }

        // ---- S = Q K^T (K row-major; b0=K[n][8kt+c], b1=K[n][8kt+c+4]) ----
        float s[8][4];
#pragma unroll
        for (int j = 0; j < 8; ++j)
#pragma unroll
            for (int q = 0; q < 4; ++q) s[j][q] = 0.f;
#pragma unroll
        for (int kt = 0; kt < 10; ++kt)
#pragma unroll
            for (int j = 0; j < 8; ++j) {
                const float* kb = &Kr[(j * 8 + g) * KR_ST + kt * 8 + c];
                mma_tf32(s[j], qf[kt],
                         __float_as_uint(kb[0]), __float_as_uint(kb[4]));
            }

        // ---- causal mask (diagonal tile only) ----
        if (k0 == q0) {
            const int row0 = wq * 16 + g;
#pragma unroll
            for (int j = 0; j < 8; ++j) {
                const int col = j * 8 + 2 * c;
                if (col     > row0)     s[j][0] = -INFINITY;
                if (col + 1 > row0)     s[j][1] = -INFINITY;
                if (col     > row0 + 8) s[j][2] = -INFINITY;
                if (col + 1 > row0 + 8) s[j][3] = -INFINITY;
            }
        }

        // ---- online softmax (rows g, g+8; quad shuffles) ----
        float tm0 = -INFINITY, tm1 = -INFINITY;
#pragma unroll
        for (int j = 0; j < 8; ++j) {
            tm0 = fmaxf(tm0, fmaxf(s[j][0], s[j][1]));
            tm1 = fmaxf(tm1, fmaxf(s[j][2], s[j][3]));
        }
        tm0 = fmaxf(tm0, __shfl_xor_sync(0xffffffff, tm0, 1));
        tm0 = fmaxf(tm0, __shfl_xor_sync(0xffffffff, tm0, 2));
        tm1 = fmaxf(tm1, __shfl_xor_sync(0xffffffff, tm1, 1));
        tm1 = fmaxf(tm1, __shfl_xor_sync(0xffffffff, tm1, 2));
        float nm0 = fmaxf(m0, tm0), nm1 = fmaxf(m1, tm1);
        float cr0 = __expf(m0 - nm0), cr1 = __expf(m1 - nm1);
        m0 = nm0; m1 = nm1;
        float ls0 = 0.f, ls1 = 0.f;
#pragma unroll
        for (int j = 0; j < 8; ++j) {
            s[j][0] = __expf(s[j][0] - m0);
            s[j][1] = __expf(s[j][1] - m0);
            s[j][2] = __expf(s[j][2] - m1);
            s[j][3] = __expf(s[j][3] - m1);
            ls0 += s[j][0] + s[j][1];
            ls1 += s[j][2] + s[j][3];
        }
        ls0 += __shfl_xor_sync(0xffffffff, ls0, 1);
        ls0 += __shfl_xor_sync(0xffffffff, ls0, 2);
        ls1 += __shfl_xor_sync(0xffffffff, ls1, 1);
        ls1 += __shfl_xor_sync(0xffffffff, ls1, 2);
        l0 = l0 * cr0 + ls0;
        l1 = l1 * cr1 + ls1;
#pragma unroll
        for (int j = 0; j < 10; ++j) {
            o[j][0] *= cr0; o[j][1] *= cr0;
            o[j][2] *= cr1; o[j][3] *= cr1;
        }

        // ---- P round trip: C-fragment -> warp smem -> A-fragment ----
        __syncwarp();
#pragma unroll
        for (int j = 0; j < 8; ++j) {
            *(float2*)&Pw[g * P_ST + j * 8 + 2 * c] =
                make_float2(f2tff(s[j][0]), f2tff(s[j][1]));
            *(float2*)&Pw[(g + 8) * P_ST + j * 8 + 2 * c] =
                make_float2(f2tff(s[j][2]), f2tff(s[j][3]));
        }
        __syncwarp();
        unsigned pa[8][4];
#pragma unroll
        for (int kt = 0; kt < 8; ++kt) {
            const float* pp = &Pw[g * P_ST + kt * 8 + c];
            pa[kt][0] = __float_as_uint(pp[0]);
            pa[kt][1] = __float_as_uint(pp[8 * P_ST]);
            pa[kt][2] = __float_as_uint(pp[4]);
            pa[kt][3] = __float_as_uint(pp[8 * P_ST + 4]);
        }

        // ---- O += P V (V row-major; b0=V[8kt+c][n], b1=V[8kt+c+4][n]) ----
#pragma unroll
        for (int kt = 0; kt < 8; ++kt)
#pragma unroll
            for (int j = 0; j < 10; ++j) {
                const int n = j * 8 + g;
                const float* vb = &Vs[(kt * 8 + c) * VS_ST + n];
                mma_tf32(o[j], pa[kt],
                         __float_as_uint(vb[0]),
                         __float_as_uint(vb[4 * VS_ST]));
            }
    }

    // ---- epilogue: normalize, tf32-round, write g_attn ----
    const float inv0 = 1.f / l0, inv1 = 1.f / l1;
    const int r0 = q0 + wq * 16 + g;
    float* outp = g_attn + (size_t)(b * S_ + r0) * (H_ * HD_) + h * HD_;
#pragma unroll
    for (int j = 0; j < 10; ++j) {
        *(float2*)&outp[j * 8 + 2 * c] =
            make_float2(f2tff(o[j][0] * inv0), f2tff(o[j][1] * inv0));
        *(float2*)&outp[(size_t)8 * (H_ * HD_) + j * 8 + 2 * c] =
            make_float2(f2tff(o[j][2] * inv1), f2tff(o[j][3] * inv1));
    }
}

// ---------------------------------------------------------------------------
// Launch
// ---------------------------------------------------------------------------
extern "C" void kernel_launch(void* const* d_in, const int* in_sizes, int n_in,
                              void* d_out, int out_size) {
    const float* hidden  = (const float*)d_in[0];
    // d_in[1] = attention_mask: pure causal, implemented structurally
    const float* scaling = (const float*)d_in[2];
    const float* qkv_w   = (const float*)d_in[3];
    const float* qkv_b   = (const float*)d_in[4];
    const float* o_w     = (const float*)d_in[5];
    const float* o_b     = (const float*)d_in[6];
    float* out = (float*)d_out;

    void *p_qkv, *p_attn, *p_hid, *p_qkvw, *p_ow;
    cudaGetSymbolAddress(&p_qkv, g_qkv);
    cudaGetSymbolAddress(&p_attn, g_attn);
    cudaGetSymbolAddress(&p_hid, g_hid);
    cudaGetSymbolAddress(&p_qkvw, g_qkvw);
    cudaGetSymbolAddress(&p_ow, g_ow);

    qscale_kernel<<<1, 128>>>(scaling);

    // Pre-round GEMM inputs to tf32 (RNA)
    {
        int n4;
        n4 = (B_ * S_ * D_) / 4;
        cvt_tf32_kernel<<<(n4 + 255) / 256, 256>>>(hidden, (float*)p_hid, n4);
        n4 = (NQKV * D_) / 4;
        cvt_tf32_kernel<<<(n4 + 255) / 256, 256>>>(qkv_w, (float*)p_qkvw, n4);
        n4 = (D_ * H_ * HD_) / 4;
        cvt_tf32_kernel<<<(n4 + 255) / 256, 256>>>(o_w, (float*)p_ow, n4);
    }

    cudaFuncSetAttribute(gemm_tf32<1, 1>,
                         cudaFuncAttributeMaxDynamicSharedMemorySize, GEMM_SMEM);
    cudaFuncSetAttribute(gemm_tf32<0, 0>,
                         cudaFuncAttributeMaxDynamicSharedMemorySize, GEMM_SMEM);

    // QKV projection (+bias, Q-scale, tf32-rounded output for flash)
    gemm_tf32<1, 1><<<dim3(NQKV / 128, (B_ * S_) / 128), 256, GEMM_SMEM>>>(
        (const float*)p_hid, (const float*)p_qkvw, qkv_b,
        (float*)p_qkv, B_ * S_, NQKV, D_);

    // Tensor-core causal flash attention
    const int smem_bytes = FL_SMEM_FLOATS * 4;   // 65536 B
    cudaFuncSetAttribute(flash_tc,
                         cudaFuncAttributeMaxDynamicSharedMemorySize, smem_bytes);
    flash_tc<<<dim3(S_ / 64, H_, B_), 128, smem_bytes>>>();

    // Output projection: [8192,1280] x [1280,1280]^T (+bias, fp32 out)
    gemm_tf32<0, 0><<<dim3(D_ / 128, (B_ * S_) / 128), 256, GEMM_SMEM>>>(
        (const float*)p_attn, (const float*)p_ow, o_b,
        out, B_ * S_, D_, D_);
}

// round 17
// speedup vs baseline: 1.6814x; 1.6814x over previous
#include <cuda_runtime.h>
#include <math.h>

#define B_  4
#define S_  2048
#define D_  1280
#define H_  16
#define HD_ 80
#define NQKV (3 * H_ * HD_)   // 3840

// Scratch (allocation-free rule: __device__ globals)
__device__ float g_qkv[(size_t)B_ * S_ * NQKV];        // 126 MB (tf32-rounded)
__device__ float g_attn[(size_t)B_ * S_ * H_ * HD_];   // 42 MB (tf32-rounded)
__device__ float g_hid[(size_t)B_ * S_ * D_];          // 42 MB (tf32-rounded)
__device__ float g_qkvw[(size_t)NQKV * D_];            // 19.7 MB (tf32-rounded)
__device__ float g_ow[(size_t)D_ * (H_ * HD_)];        // 6.6 MB (tf32-rounded)
__device__ float g_qscale[HD_];

// ---------------------------------------------------------------------------
// Helpers
// ---------------------------------------------------------------------------
__device__ __forceinline__ unsigned f2tf(float x) {
    unsigned r;
    asm("cvt.rna.tf32.f32 %0, %1;" : "=r"(r) : "f"(x));
    return r;
}
__device__ __forceinline__ float f2tff(float x) {
    return __uint_as_float(f2tf(x));
}
__device__ __forceinline__ void mma_tf32(float* d, const unsigned* a,
                                         unsigned b0, unsigned b1) {
    asm volatile(
        "mma.sync.aligned.m16n8k8.row.col.f32.tf32.tf32.f32 "
        "{%0,%1,%2,%3}, {%4,%5,%6,%7}, {%8,%9}, {%0,%1,%2,%3};"
        : "+f"(d[0]), "+f"(d[1]), "+f"(d[2]), "+f"(d[3])
        : "r"(a[0]), "r"(a[1]), "r"(a[2]), "r"(a[3]), "r"(b0), "r"(b1));
}
__device__ __forceinline__ void cp_async16(unsigned dst, const float* src) {
    asm volatile("cp.async.cg.shared.global [%0], [%1], 16;"
                 :: "r"(dst), "l"(src));
}
__device__ __forceinline__ void cp_commit() {
    asm volatile("cp.async.commit_group;");
}
template <int N>
__device__ __forceinline__ void cp_wait() {
    asm volatile("cp.async.wait_group %0;" :: "n"(N));
}

// ---------------------------------------------------------------------------
// Pre-pass: tf32-round an fp32 array (element count divisible by 4)
// ---------------------------------------------------------------------------
__global__ void cvt_tf32_kernel(const float* __restrict__ src,
                                float* __restrict__ dst, int n4) {
    int i = blockIdx.x * blockDim.x + threadIdx.x;
    if (i < n4) {
        float4 v = ((const float4*)src)[i];
        ((float4*)dst)[i] = make_float4(f2tff(v.x), f2tff(v.y),
                                        f2tff(v.z), f2tff(v.w));
    }
}

// ---------------------------------------------------------------------------
// Per-dim query scale: softplus(scaling) * log2(e) / sqrt(HD)
// ---------------------------------------------------------------------------
__global__ void qscale_kernel(const float* __restrict__ scaling) {
    int i = threadIdx.x;
    if (i < HD_) {
        float x = scaling[i];
        float sp = (x > 20.f) ? x : log1pf(expf(x));
        g_qscale[i] = sp * 1.4426950408889634f * rsqrtf((float)HD_);
    }
}

// ---------------------------------------------------------------------------
// TF32 tensor-core GEMM (R13 config — measured best, DO NOT TOUCH):
// 4-stage cp.async, KT=16/stage, wait<2> (>=2 groups outstanding).
// C = A·B^T + bias; A,B K-major, pre-rounded to tf32. 128x128 tile,
// 256 threads, warp tile 32x64, m16n8k8. smem [row][k] stride 20;
// fragment LDS banks (20g+c) all-distinct.
// ROUND_OUT: tf32-round epilogue output (QKV -> flash consumption).
// ---------------------------------------------------------------------------
#define GST  20
#define GSTG (128 * GST)            // 2560 floats per operand-stage
#define NSTG 4
#define GEMM_SMEM (2 * NSTG * GSTG * 4)   // 81920 B

template <int APPLY_QSCALE, int ROUND_OUT>
__global__ __launch_bounds__(256, 2)
void gemm_tf32(const float* __restrict__ A, const float* __restrict__ Bm,
               const float* __restrict__ bias, float* __restrict__ C,
               int M, int N, int K) {
    extern __shared__ float gsm[];
    float* smA = gsm;                    // [NSTG][128][GST]
    float* smB = gsm + NSTG * GSTG;

    const int tid  = threadIdx.x;
    const int lane = tid & 31;
    const int wid  = tid >> 5;
    const int wm   = wid & 3;
    const int wn   = wid >> 2;
    const int g    = lane >> 2;
    const int c    = lane & 3;

    const int m0 = blockIdx.y * 128;
    const int n0 = blockIdx.x * 128;

    const int lrow = tid >> 1;       // 0..127
    const int lc   = (tid & 1) * 8;  // 0 or 8

    const float* Ap = A  + (size_t)(m0 + lrow) * K + lc;
    const float* Bp = Bm + (size_t)(n0 + lrow) * K + lc;

    const unsigned sA = (unsigned)__cvta_generic_to_shared(smA)
                        + (lrow * GST + lc) * 4;
    const unsigned sB = (unsigned)__cvta_generic_to_shared(smB)
                        + (lrow * GST + lc) * 4;

    float acc[2][8][4];
#pragma unroll
    for (int i = 0; i < 2; ++i)
#pragma unroll
        for (int j = 0; j < 8; ++j)
#pragma unroll
            for (int q = 0; q < 4; ++q) acc[i][j][q] = 0.f;

    const int tiles = K >> 4;

    // prologue: stages 0..2
#pragma unroll
    for (int s = 0; s < NSTG - 1; ++s) {
        const int k0 = s * 16;
        cp_async16(sA + s * GSTG * 4,      Ap + k0);
        cp_async16(sA + s * GSTG * 4 + 16, Ap + k0 + 4);
        cp_async16(sB + s * GSTG * 4,      Bp + k0);
        cp_async16(sB + s * GSTG * 4 + 16, Bp + k0 + 4);
        cp_commit();
    }

    for (int i = 0; i < tiles; ++i) {
        cp_wait<NSTG - 2>();
        __syncthreads();

        const int st = i & (NSTG - 1);
        const float* Asp = &smA[st * GSTG];
        const float* Bsp = &smB[st * GSTG];
#pragma unroll
        for (int ks = 0; ks < 2; ++ks) {
            const int kk = ks * 8;
            unsigned af[2][4];
#pragma unroll
            for (int ii = 0; ii < 2; ++ii) {
                const float* ab = &Asp[(wm * 32 + ii * 16 + g) * GST + kk + c];
                af[ii][0] = __float_as_uint(ab[0]);
                af[ii][1] = __float_as_uint(ab[8 * GST]);
                af[ii][2] = __float_as_uint(ab[4]);
                af[ii][3] = __float_as_uint(ab[8 * GST + 4]);
            }
#pragma unroll
            for (int j = 0; j < 8; ++j) {
                const float* bb = &Bsp[(wn * 64 + j * 8 + g) * GST + kk + c];
                unsigned b0 = __float_as_uint(bb[0]);
                unsigned b1 = __float_as_uint(bb[4]);
                mma_tf32(acc[0][j], af[0], b0, b1);
                mma_tf32(acc[1][j], af[1], b0, b1);
            }
        }

        const int nf = i + NSTG - 1;
        if (nf < tiles) {
            const int ns = nf & (NSTG - 1);
            const int k0 = nf * 16;
            cp_async16(sA + ns * GSTG * 4,      Ap + k0);
            cp_async16(sA + ns * GSTG * 4 + 16, Ap + k0 + 4);
            cp_async16(sB + ns * GSTG * 4,      Bp + k0);
            cp_async16(sB + ns * GSTG * 4 + 16, Bp + k0 + 4);
        }
        cp_commit();
    }

    // Epilogue: + bias, optional Q scaling, optional tf32 rounding
#pragma unroll
    for (int j = 0; j < 8; ++j) {
        const int col = n0 + wn * 64 + j * 8 + c * 2;
        float b0 = bias[col], b1 = bias[col + 1];
        float q0 = 1.f, q1 = 1.f;
        if (APPLY_QSCALE && col < H_ * HD_) {
            q0 = g_qscale[col % HD_];
            q1 = g_qscale[(col + 1) % HD_];
        }
#pragma unroll
        for (int i = 0; i < 2; ++i) {
            const int r0 = m0 + wm * 32 + i * 16 + g;
            float2 o0, o1;
            o0.x = (acc[i][j][0] + b0) * q0;
            o0.y = (acc[i][j][1] + b1) * q1;
            o1.x = (acc[i][j][2] + b0) * q0;
            o1.y = (acc[i][j][3] + b1) * q1;
            if (ROUND_OUT) {
                o0.x = f2tff(o0.x); o0.y = f2tff(o0.y);
                o1.x = f2tff(o1.x); o1.y = f2tff(o1.y);
            }
            *(float2*)&C[(size_t)r0 * N + col]       = o0;
            *(float2*)&C[(size_t)(r0 + 8) * N + col] = o1;
        }
    }
}

// ---------------------------------------------------------------------------
// Tensor-core causal flash attention (R13 config) at OCCUPANCY 3:
// 64 KB smem/CTA x3 = 192 KB < 228 KB; third resident CTA covers the
// serial stage->wait->compute bubble per tile.
// BQ=64 (4 warps x 16 rows), BK=64. 1280 16B-chunks per tile.
// Q,K row-major stride 84 (fragment banks 20g+c: distinct).
// V row-major stride 88 (fragment banks 24c+g: distinct).
// grid = (S/64 [reversed], H, B), block = 128.
// ---------------------------------------------------------------------------
#define QS_ST 84
#define KR_ST 84
#define VS_ST 88
#define P_ST  68
#define QS_FLOATS (64 * QS_ST)          // 5376
#define KR_FLOATS (64 * KR_ST)          // 5376
#define VS_FLOATS (64 * VS_ST)          // 5632
#define FL_SMEM_FLOATS (QS_FLOATS + KR_FLOATS + VS_FLOATS)   // 16384

__global__ __launch_bounds__(128, 3)
void flash_tc() {
    extern __shared__ float sm[];
    float* Qs = sm;                     // [64][84]; reused as P after Q->regs
    float* Kr = sm + QS_FLOATS;         // [64][84]
    float* Vs = Kr + KR_FLOATS;         // [64][88]

    const int t    = threadIdx.x;
    const int lane = t & 31;
    const int wq   = t >> 5;
    const int g    = lane >> 2;
    const int c    = lane & 3;
    const int qt   = gridDim.x - 1 - blockIdx.x;   // heavy blocks first
    const int q0   = qt * 64;
    const int h    = blockIdx.y;
    const int b    = blockIdx.z;

    const unsigned sQ = (unsigned)__cvta_generic_to_shared(Qs);
    const unsigned sK = (unsigned)__cvta_generic_to_shared(Kr);
    const unsigned sV = (unsigned)__cvta_generic_to_shared(Vs);

    // Stage Q via cp.async: 64 rows x 20 16B-chunks = 1280 chunks
    {
        const float* qg = g_qkv + (size_t)(b * S_ + q0) * NQKV + h * HD_;
        for (int i = t; i < 1280; i += 128) {
            int r = i / 20, q4 = (i % 20) * 4;
            cp_async16(sQ + (r * QS_ST + q4) * 4, qg + (size_t)r * NQKV + q4);
        }
        cp_commit();
        cp_wait<0>();
        __syncthreads();
    }

    // Q fragments (A layout)
    unsigned qf[10][4];
#pragma unroll
    for (int kt = 0; kt < 10; ++kt) {
        const float* qp = &Qs[(wq * 16 + g) * QS_ST + kt * 8 + c];
        qf[kt][0] = __float_as_uint(qp[0]);
        qf[kt][1] = __float_as_uint(qp[8 * QS_ST]);
        qf[kt][2] = __float_as_uint(qp[4]);
        qf[kt][3] = __float_as_uint(qp[8 * QS_ST + 4]);
    }

    float m0 = -INFINITY, m1 = -INFINITY, l0 = 0.f, l1 = 0.f;
    float o[10][4];
#pragma unroll
    for (int j = 0; j < 10; ++j)
#pragma unroll
        for (int q = 0; q < 4; ++q) o[j][q] = 0.f;

    float* Pw = sm + wq * (16 * P_ST);   // warp-private, overlaps Qs (safe:
                                         // qf cached in regs before loop)

    const int ntiles = qt + 1;
    for (int kt0 = 0; kt0 < ntiles; ++kt0) {
        const int k0 = kt0 * 64;
        __syncthreads();   // previous tile fully consumed before overwrite
        // Stage K,V via cp.async: 1280 chunks each
        {
            const float* kg = g_qkv + (size_t)(b * S_ + k0) * NQKV
                              + H_ * HD_ + h * HD_;
            const float* vg = kg + H_ * HD_;
            for (int i = t; i < 1280; i += 128) {
                int r = i / 20, q4 = (i % 20) * 4;
                size_t off = (size_t)r * NQKV + q4;
                cp_async16(sK + (r * KR_ST + q4) * 4, kg + off);
                cp_async16(sV + (r * VS_ST + q4) * 4, vg + off);
            }
            cp_commit();
            cp_wait<0>();
            __syncthreads();
        }

        // ---- S = Q K^T (K row-major; b0=K[n][8kt+c], b1=K[n][8kt+c+4]) ----
        float s[8][4];
#pragma unroll
        for (int j = 0; j < 8; ++j)
#pragma unroll
            for (int q = 0; q < 4; ++q) s[j][q] = 0.f;
#pragma unroll
        for (int kt = 0; kt < 10; ++kt)
#pragma unroll
            for (int j = 0; j < 8; ++j) {
                const float* kb = &Kr[(j * 8 + g) * KR_ST + kt * 8 + c];
                mma_tf32(s[j], qf[kt],
                         __float_as_uint(kb[0]), __float_as_uint(kb[4]));
            }

        // ---- causal mask (diagonal tile only) ----
        if (k0 == q0) {
            const int row0 = wq * 16 + g;
#pragma unroll
            for (int j = 0; j < 8; ++j) {
                const int col = j * 8 + 2 * c;
                if (col     > row0)     s[j][0] = -INFINITY;
                if (col + 1 > row0)     s[j][1] = -INFINITY;
                if (col     > row0 + 8) s[j][2] = -INFINITY;
                if (col + 1 > row0 + 8) s[j][3] = -INFINITY;
            }
        }

        // ---- online softmax (rows g, g+8; quad shuffles) ----
        float tm0 = -INFINITY, tm1 = -INFINITY;
#pragma unroll
        for (int j = 0; j < 8; ++j) {
            tm0 = fmaxf(tm0, fmaxf(s[j][0], s[j][1]));
            tm1 = fmaxf(tm1, fmaxf(s[j][2], s[j][3]));
        }
        tm0 = fmaxf(tm0, __shfl_xor_sync(0xffffffff, tm0, 1));
        tm0 = fmaxf(tm0, __shfl_xor_sync(0xffffffff, tm0, 2));
        tm1 = fmaxf(tm1, __shfl_xor_sync(0xffffffff, tm1, 1));
        tm1 = fmaxf(tm1, __shfl_xor_sync(0xffffffff, tm1, 2));
        float nm0 = fmaxf(m0, tm0), nm1 = fmaxf(m1, tm1);
        float cr0 = __expf(m0 - nm0), cr1 = __expf(m1 - nm1);
        m0 = nm0; m1 = nm1;
        float ls0 = 0.f, ls1 = 0.f;
#pragma unroll
        for (int j = 0; j < 8; ++j) {
            s[j][0] = __expf(s[j][0] - m0);
            s[j][1] = __expf(s[j][1] - m0);
            s[j][2] = __expf(s[j][2] - m1);
            s[j][3] = __expf(s[j][3] - m1);
            ls0 += s[j][0] + s[j][1];
            ls1 += s[j][2] + s[j][3];
        }
        ls0 += __shfl_xor_sync(0xffffffff, ls0, 1);
        ls0 += __shfl_xor_sync(0xffffffff, ls0, 2);
        ls1 += __shfl_xor_sync(0xffffffff, ls1, 1);
        ls1 += __shfl_xor_sync(0xffffffff, ls1, 2);
        l0 = l0 * cr0 + ls0;
        l1 = l1 * cr1 + ls1;
#pragma unroll
        for (int j = 0; j < 10; ++j) {
            o[j][0] *= cr0; o[j][1] *= cr0;
            o[j][2] *= cr1; o[j][3] *= cr1;
        }

        // ---- P round trip: C-fragment -> warp smem -> A-fragment ----
        __syncwarp();
#pragma unroll
        for (int j = 0; j < 8; ++j) {
            *(float2*)&Pw[g * P_ST + j * 8 + 2 * c] =
                make_float2(f2tff(s[j][0]), f2tff(s[j][1]));
            *(float2*)&Pw[(g + 8) * P_ST + j * 8 + 2 * c] =
                make_float2(f2tff(s[j][2]), f2tff(s[j][3]));
        }
        __syncwarp();
        unsigned pa[8][4];
#pragma unroll
        for (int kt = 0; kt < 8; ++kt) {
            const float* pp = &Pw[g * P_ST + kt * 8 + c];
            pa[kt][0] = __float_as_uint(pp[0]);
            pa[kt][1] = __float_as_uint(pp[8 * P_ST]);
            pa[kt][2] = __float_as_uint(pp[4]);
            pa[kt][3] = __float_as_uint(pp[8 * P_ST + 4]);
        }

        // ---- O += P V (V row-major; b0=V[8kt+c][n], b1=V[8kt+c+4][n]) ----
#pragma unroll
        for (int kt = 0; kt < 8; ++kt)
#pragma unroll
            for (int j = 0; j < 10; ++j) {
                const int n = j * 8 + g;
                const float* vb = &Vs[(kt * 8 + c) * VS_ST + n];
                mma_tf32(o[j], pa[kt],
                         __float_as_uint(vb[0]),
                         __float_as_uint(vb[4 * VS_ST]));
            }
    }

    // ---- epilogue: normalize, tf32-round, write g_attn ----
    const float inv0 = 1.f / l0, inv1 = 1.f / l1;
    const int r0 = q0 + wq * 16 + g;
    float* outp = g_attn + (size_t)(b * S_ + r0) * (H_ * HD_) + h * HD_;
#pragma unroll
    for (int j = 0; j < 10; ++j) {
        *(float2*)&outp[j * 8 + 2 * c] =
            make_float2(f2tff(o[j][0] * inv0), f2tff(o[j][1] * inv0));
        *(float2*)&outp[(size_t)8 * (H_ * HD_) + j * 8 + 2 * c] =
            make_float2(f2tff(o[j][2] * inv1), f2tff(o[j][3] * inv1));
    }
}

// ---------------------------------------------------------------------------
// Launch
// ---------------------------------------------------------------------------
extern "C" void kernel_launch(void* const* d_in, const int* in_sizes, int n_in,
                              void* d_out, int out_size) {
    const float* hidden  = (const float*)d_in[0];
    // d_in[1] = attention_mask: pure causal, implemented structurally
    const float* scaling = (const float*)d_in[2];
    const float* qkv_w   = (const float*)d_in[3];
    const float* qkv_b   = (const float*)d_in[4];
    const float* o_w     = (const float*)d_in[5];
    const float* o_b     = (const float*)d_in[6];
    float* out = (float*)d_out;

    void *p_qkv, *p_attn, *p_hid, *p_qkvw, *p_ow;
    cudaGetSymbolAddress(&p_qkv, g_qkv);
    cudaGetSymbolAddress(&p_attn, g_attn);
    cudaGetSymbolAddress(&p_hid, g_hid);
    cudaGetSymbolAddress(&p_qkvw, g_qkvw);
    cudaGetSymbolAddress(&p_ow, g_ow);

    qscale_kernel<<<1, 128>>>(scaling);

    // Pre-round GEMM inputs to tf32 (RNA)
    {
        int n4;
        n4 = (B_ * S_ * D_) / 4;
        cvt_tf32_kernel<<<(n4 + 255) / 256, 256>>>(hidden, (float*)p_hid, n4);
        n4 = (NQKV * D_) / 4;
        cvt_tf32_kernel<<<(n4 + 255) / 256, 256>>>(qkv_w, (float*)p_qkvw, n4);
        n4 = (D_ * H_ * HD_) / 4;
        cvt_tf32_kernel<<<(n4 + 255) / 256, 256>>>(o_w, (float*)p_ow, n4);
    }

    cudaFuncSetAttribute(gemm_tf32<1, 1>,
                         cudaFuncAttributeMaxDynamicSharedMemorySize, GEMM_SMEM);
    cudaFuncSetAttribute(gemm_tf32<0, 0>,
                         cudaFuncAttributeMaxDynamicSharedMemorySize, GEMM_SMEM);

    // QKV projection (+bias, Q-scale, tf32-rounded output for flash)
    gemm_tf32<1, 1><<<dim3(NQKV / 128, (B_ * S_) / 128), 256, GEMM_SMEM>>>(
        (const float*)p_hid, (const float*)p_qkvw, qkv_b,
        (float*)p_qkv, B_ * S_, NQKV, D_);

    // Tensor-core causal flash attention (occupancy 3)
    const int smem_bytes = FL_SMEM_FLOATS * 4;   // 65536 B
    cudaFuncSetAttribute(flash_tc,
                         cudaFuncAttributeMaxDynamicSharedMemorySize, smem_bytes);
    flash_tc<<<dim3(S_ / 64, H_, B_), 128, smem_bytes>>>();

    // Output projection: [8192,1280] x [1280,1280]^T (+bias, fp32 out)
    gemm_tf32<0, 0><<<dim3(D_ / 128, (B_ * S_) / 128), 256, GEMM_SMEM>>>(
        (const float*)p_attn, (const float*)p_ow, o_b,
        out, B_ * S_, D_, D_);
}